// round 13
// baseline (speedup 1.0000x reference)
#include <cuda_runtime.h>
#include <cuda_fp16.h>
#include <cstdint>

#define HDIM 2048
#define NTOK 8192          // B*S
#define NTHREADS 512
#define NCTAS 456          // 152 SMs * 3 resident CTAs
#define EPSV 1e-6f

__device__ __forceinline__ float4 ldcs4(const float* p) {
    float4 v;
    asm volatile("ld.global.cs.v4.f32 {%0,%1,%2,%3}, [%4];"
                 : "=f"(v.x), "=f"(v.y), "=f"(v.z), "=f"(v.w) : "l"(p));
    return v;
}
__device__ __forceinline__ void stcs4(float* p, float4 v) {
    asm volatile("st.global.cs.v4.f32 [%0], {%1,%2,%3,%4};"
                 :: "l"(p), "f"(v.x), "f"(v.y), "f"(v.z), "f"(v.w));
}
__device__ __forceinline__ float tanh_fast(float x) {
    float y; asm("tanh.approx.f32 %0, %1;" : "=f"(y) : "f"(x)); return y;
}

// dot of a float4 against a packed half2-pair (8 bytes of q)
__device__ __forceinline__ float dotq(float4 x, uint2 u) {
    float2 f0 = __half22float2(*(__half2*)&u.x);
    float2 f1 = __half22float2(*(__half2*)&u.y);
    return x.x*f0.x + x.y*f0.y + x.z*f1.x + x.w*f1.y;
}
__device__ __forceinline__ float dot4(float4 a, float4 b) {
    return a.x*b.x + a.y*b.y + a.z*b.z + a.w*b.w;
}

__global__ __launch_bounds__(NTHREADS, 3)
void altup_v9_kernel(const float* __restrict__ hs,     // [4, NTOK, H]
                     const float* __restrict__ act,    // [NTOK, H]
                     const float* __restrict__ w,      // [H]
                     const float* __restrict__ rw,     // [4, H]
                     const float* __restrict__ pw,     // [16, 4]
                     const float* __restrict__ cw,     // [4, 4]
                     const float* __restrict__ oscale, // [H]
                     float* __restrict__ out)          // [4, NTOK, H]
{
    const int tid = threadIdx.x;
    const int h4  = tid * 4;
    const int warp = tid >> 5, lane = tid & 31;
    const float inv_h = 1.0f / (float)HDIM;

    __shared__ __align__(16) __half2 q_h[4][HDIM/2];   // fp16 fused weights, 16KB
    __shared__ float red[2][16][10];                    // ping-pong partials
    __shared__ float pw_s[64];
    __shared__ float cw_s[16];

    // ---- one-time staging: q = w * rw, compressed to fp16 ----
    #pragma unroll
    for (int r = 0; r < 4; r++) {
        float4 wv = __ldg((const float4*)(w + h4));
        float4 rv = __ldg((const float4*)(rw + r*HDIM + h4));
        q_h[r][tid*2 + 0] = __float22half2_rn(make_float2(wv.x*rv.x, wv.y*rv.y));
        q_h[r][tid*2 + 1] = __float22half2_rn(make_float2(wv.z*rv.z, wv.w*rv.w));
    }
    if (tid < 64) pw_s[tid] = pw[tid];
    if (tid < 16) cw_s[tid] = cw[tid];
    const float4 sv = __ldg((const float4*)(oscale + h4));
    __syncthreads();

    int par = 0;
    for (int t = blockIdx.x; t < NTOK; t += NCTAS, par ^= 1) {
        // ---- phase 1: reduction streams ----
        float4 x0 = ldcs4(hs  + (size_t)t * HDIM + h4);
        float4 av = ldcs4(act + (size_t)t * HDIM + h4);

        float p[10];
        p[0] = dot4(x0, x0);
        p[5] = dot4(av, av);
        {
            uint2 u0 = *(const uint2*)&q_h[0][tid*2];
            uint2 u1 = *(const uint2*)&q_h[1][tid*2];
            p[1] = dotq(x0, u0);  p[2] = dotq(x0, u1);
            p[6] = dotq(av, u0);  p[7] = dotq(av, u1);
        }
        {
            uint2 u2 = *(const uint2*)&q_h[2][tid*2];
            uint2 u3 = *(const uint2*)&q_h[3][tid*2];
            p[3] = dotq(x0, u2);  p[4] = dotq(x0, u3);
            p[8] = dotq(av, u2);  p[9] = dotq(av, u3);
        }

        // ---- prefetch phase-2 streams before the reduce ----
        float4 x1 = ldcs4(hs + ((size_t)1*NTOK + t)*HDIM + h4);
        float4 x2 = ldcs4(hs + ((size_t)2*NTOK + t)*HDIM + h4);
        float4 x3 = ldcs4(hs + ((size_t)3*NTOK + t)*HDIM + h4);

        // ---- warp shuffle reduce, write partials, ONE barrier ----
        #pragma unroll
        for (int k = 0; k < 10; k++) {
            #pragma unroll
            for (int o = 16; o > 0; o >>= 1)
                p[k] += __shfl_xor_sync(0xffffffffu, p[k], o);
        }
        if (lane == 0) {
            #pragma unroll
            for (int k = 0; k < 10; k++) red[par][warp][k] = p[k];
        }
        __syncthreads();

        // ---- EVERY warp independently: finalize sums + coef math ----
        float f = 0.f;
        if (lane < 10) {
            #pragma unroll
            for (int wi = 0; wi < 16; wi++) f += red[par][wi][lane];
        }
        float fin[10];
        #pragma unroll
        for (int k = 0; k < 10; k++)
            fin[k] = __shfl_sync(0xffffffffu, f, k);

        float g0 = rsqrtf(fin[0] * inv_h + EPSV) * inv_h;
        float g1 = rsqrtf(fin[5] * inv_h + EPSV) * inv_h;

        float cf;
        if (lane < 16) {
            float s = 0.f;
            #pragma unroll
            for (int n = 0; n < 4; n++)
                s = fmaf(tanh_fast(fin[1 + n] * g0), pw_s[lane*4 + n], s);
            cf = s;
        } else {
            int n = lane & 3;
            float s = 1.0f;
            #pragma unroll
            for (int k = 0; k < 4; k++)
                s = fmaf(tanh_fast(fin[6 + k] * g1), cw_s[n*4 + k], s);
            cf = s;
        }

        // ---- phase 2: elementwise combine, coefs via shuffles ----
        float xc[4][4];
        xc[0][0]=x0.x; xc[0][1]=x0.y; xc[0][2]=x0.z; xc[0][3]=x0.w;
        xc[1][0]=x1.x; xc[1][1]=x1.y; xc[1][2]=x1.z; xc[1][3]=x1.w;
        xc[2][0]=x2.x; xc[2][1]=x2.y; xc[2][2]=x2.z; xc[2][3]=x2.w;
        xc[3][0]=x3.x; xc[3][1]=x3.y; xc[3][2]=x3.z; xc[3][3]=x3.w;
        const float ac[4] = {av.x, av.y, av.z, av.w};
        const float sc[4] = {sv.x, sv.y, sv.z, sv.w};

        float innov[4];
        {
            const float c0  = __shfl_sync(0xffffffffu, cf, 0);
            const float c1  = __shfl_sync(0xffffffffu, cf, 1);
            const float c2  = __shfl_sync(0xffffffffu, cf, 2);
            const float c3  = __shfl_sync(0xffffffffu, cf, 3);
            const float cc0 = __shfl_sync(0xffffffffu, cf, 16);
            float4 o4;
            float* op = &o4.x;
            #pragma unroll
            for (int comp = 0; comp < 4; comp++) {
                float s = xc[0][comp];
                s = fmaf(c0, xc[0][comp], s);
                s = fmaf(c1, xc[1][comp], s);
                s = fmaf(c2, xc[2][comp], s);
                s = fmaf(c3, xc[3][comp], s);
                innov[comp] = ac[comp] - s;
                op[comp] = (s + innov[comp]*cc0) * sc[comp];
            }
            stcs4(out + ((size_t)t)*HDIM + h4, o4);
        }
        #pragma unroll
        for (int j = 1; j < 4; j++) {
            const float c0  = __shfl_sync(0xffffffffu, cf, j*4 + 0);
            const float c1  = __shfl_sync(0xffffffffu, cf, j*4 + 1);
            const float c2  = __shfl_sync(0xffffffffu, cf, j*4 + 2);
            const float c3  = __shfl_sync(0xffffffffu, cf, j*4 + 3);
            const float ccj = __shfl_sync(0xffffffffu, cf, 16 + j);
            float4 o4;
            float* op = &o4.x;
            #pragma unroll
            for (int comp = 0; comp < 4; comp++) {
                float s = xc[j][comp];
                s = fmaf(c0, xc[0][comp], s);
                s = fmaf(c1, xc[1][comp], s);
                s = fmaf(c2, xc[2][comp], s);
                s = fmaf(c3, xc[3][comp], s);
                op[comp] = (s + innov[comp]*ccj) * sc[comp];
            }
            stcs4(out + ((size_t)j*NTOK + t)*HDIM + h4, o4);
        }
        // no trailing barrier: red ping-pongs by parity; same-parity reuse is
        // separated by the single barrier of the intervening iteration.
    }
}

extern "C" void kernel_launch(void* const* d_in, const int* in_sizes, int n_in,
                              void* d_out, int out_size)
{
    const float* hs     = (const float*)d_in[0];
    const float* act    = (const float*)d_in[1];
    const float* w      = (const float*)d_in[2];
    const float* rw     = (const float*)d_in[3];
    const float* pw     = (const float*)d_in[4];
    const float* cw     = (const float*)d_in[5];
    const float* oscale = (const float*)d_in[6];
    float* out = (float*)d_out;

    altup_v9_kernel<<<NCTAS, NTHREADS>>>(hs, act, w, rw, pw, cw, oscale, out);
}

// round 14
// speedup vs baseline: 1.0229x; 1.0229x over previous
#include <cuda_runtime.h>
#include <cstdint>

#define HDIM 2048
#define NTOK 8192          // B*S
#define NTHREADS 512
#define NCTAS 456          // 152 SMs * 3 resident CTAs
#define EPSV 1e-6f

__device__ __forceinline__ float4 ldcs4(const float* p) {
    float4 v;
    asm volatile("ld.global.cs.v4.f32 {%0,%1,%2,%3}, [%4];"
                 : "=f"(v.x), "=f"(v.y), "=f"(v.z), "=f"(v.w) : "l"(p));
    return v;
}
__device__ __forceinline__ void stcs4(float* p, float4 v) {
    asm volatile("st.global.cs.v4.f32 [%0], {%1,%2,%3,%4};"
                 :: "l"(p), "f"(v.x), "f"(v.y), "f"(v.z), "f"(v.w));
}
__device__ __forceinline__ float tanh_fast(float x) {
    float y; asm("tanh.approx.f32 %0, %1;" : "=f"(y) : "f"(x)); return y;
}
__device__ __forceinline__ float dot4(float4 a, float4 b) {
    return a.x*b.x + a.y*b.y + a.z*b.z + a.w*b.w;
}

__global__ __launch_bounds__(NTHREADS, 3)
void altup_v10_kernel(const float* __restrict__ hs,     // [4, NTOK, H]
                      const float* __restrict__ act,    // [NTOK, H]
                      const float* __restrict__ w,      // [H]
                      const float* __restrict__ rw,     // [4, H]
                      const float* __restrict__ pw,     // [16, 4]
                      const float* __restrict__ cw,     // [4, 4]
                      const float* __restrict__ oscale, // [H]
                      float* __restrict__ out)          // [4, NTOK, H]
{
    const int tid = threadIdx.x;
    const int h4  = tid * 4;
    const int warp = tid >> 5, lane = tid & 31;
    const float inv_h = 1.0f / (float)HDIM;

    __shared__ float q_s[4][HDIM];       // fused router weights w*rw[n]  (32 KB)
    __shared__ float red[2][16][10];     // ping-pong partial sums
    __shared__ float pw_s[64];
    __shared__ float cw_s[16];

    // ---- one-time staging: q = w * rw ----
    #pragma unroll
    for (int r = 0; r < 4; r++) {
        float4 wv = __ldg((const float4*)(w + h4));
        float4 rv = __ldg((const float4*)(rw + r*HDIM + h4));
        *(float4*)&q_s[r][h4] = make_float4(wv.x*rv.x, wv.y*rv.y, wv.z*rv.z, wv.w*rv.w);
    }
    if (tid < 64) pw_s[tid] = pw[tid];
    if (tid < 16) cw_s[tid] = cw[tid];
    const float4 sv = __ldg((const float4*)(oscale + h4));
    __syncthreads();

    int par = 0;
    for (int t = blockIdx.x; t < NTOK; t += NCTAS, par ^= 1) {
        // ---- ALL 5 stream loads back-to-back: one DRAM round trip, MLP=5 ----
        float4 x0 = ldcs4(hs  + (size_t)t * HDIM + h4);
        float4 av = ldcs4(act + (size_t)t * HDIM + h4);
        float4 x1 = ldcs4(hs + ((size_t)1*NTOK + t)*HDIM + h4);
        float4 x2 = ldcs4(hs + ((size_t)2*NTOK + t)*HDIM + h4);
        float4 x3 = ldcs4(hs + ((size_t)3*NTOK + t)*HDIM + h4);

        // ---- dots against smem-resident fused weights (consume x0/av) ----
        float p[10];
        {
            float4 q0 = *(const float4*)&q_s[0][h4];
            float4 q1 = *(const float4*)&q_s[1][h4];
            p[0] = dot4(x0, x0);
            p[1] = dot4(x0, q0);  p[2] = dot4(x0, q1);
            p[5] = dot4(av, av);
            p[6] = dot4(av, q0);  p[7] = dot4(av, q1);
        }
        {
            float4 q2 = *(const float4*)&q_s[2][h4];
            float4 q3 = *(const float4*)&q_s[3][h4];
            p[3] = dot4(x0, q2);  p[4] = dot4(x0, q3);
            p[8] = dot4(av, q2);  p[9] = dot4(av, q3);
        }

        // ---- warp shuffle reduce, write partials, ONE barrier ----
        #pragma unroll
        for (int k = 0; k < 10; k++) {
            #pragma unroll
            for (int o = 16; o > 0; o >>= 1)
                p[k] += __shfl_xor_sync(0xffffffffu, p[k], o);
        }
        if (lane == 0) {
            #pragma unroll
            for (int k = 0; k < 10; k++) red[par][warp][k] = p[k];
        }
        __syncthreads();

        // ---- EVERY warp independently: finalize sums + coef math ----
        float f = 0.f;
        if (lane < 10) {
            #pragma unroll
            for (int wi = 0; wi < 16; wi++) f += red[par][wi][lane];
        }
        float fin[10];
        #pragma unroll
        for (int k = 0; k < 10; k++)
            fin[k] = __shfl_sync(0xffffffffu, f, k);

        float g0 = rsqrtf(fin[0] * inv_h + EPSV) * inv_h;
        float g1 = rsqrtf(fin[5] * inv_h + EPSV) * inv_h;

        // lanes 0..15: c[j][i] (lane = j*4+i); lanes 16..19: cc[lane-16]
        float cf;
        if (lane < 16) {
            float s = 0.f;
            #pragma unroll
            for (int n = 0; n < 4; n++)
                s = fmaf(tanh_fast(fin[1 + n] * g0), pw_s[lane*4 + n], s);
            cf = s;
        } else {
            int n = lane & 3;
            float s = 1.0f;
            #pragma unroll
            for (int k = 0; k < 4; k++)
                s = fmaf(tanh_fast(fin[6 + k] * g1), cw_s[n*4 + k], s);
            cf = s;
        }

        // ---- phase 2: elementwise combine, coefs via shuffles ----
        float xc[4][4];
        xc[0][0]=x0.x; xc[0][1]=x0.y; xc[0][2]=x0.z; xc[0][3]=x0.w;
        xc[1][0]=x1.x; xc[1][1]=x1.y; xc[1][2]=x1.z; xc[1][3]=x1.w;
        xc[2][0]=x2.x; xc[2][1]=x2.y; xc[2][2]=x2.z; xc[2][3]=x2.w;
        xc[3][0]=x3.x; xc[3][1]=x3.y; xc[3][2]=x3.z; xc[3][3]=x3.w;
        const float ac[4] = {av.x, av.y, av.z, av.w};
        const float sc[4] = {sv.x, sv.y, sv.z, sv.w};

        float innov[4];
        {
            const float c0  = __shfl_sync(0xffffffffu, cf, 0);
            const float c1  = __shfl_sync(0xffffffffu, cf, 1);
            const float c2  = __shfl_sync(0xffffffffu, cf, 2);
            const float c3  = __shfl_sync(0xffffffffu, cf, 3);
            const float cc0 = __shfl_sync(0xffffffffu, cf, 16);
            float4 o4;
            float* op = &o4.x;
            #pragma unroll
            for (int comp = 0; comp < 4; comp++) {
                float s = xc[0][comp];
                s = fmaf(c0, xc[0][comp], s);
                s = fmaf(c1, xc[1][comp], s);
                s = fmaf(c2, xc[2][comp], s);
                s = fmaf(c3, xc[3][comp], s);
                innov[comp] = ac[comp] - s;
                op[comp] = (s + innov[comp]*cc0) * sc[comp];
            }
            stcs4(out + ((size_t)t)*HDIM + h4, o4);
        }
        #pragma unroll
        for (int j = 1; j < 4; j++) {
            const float c0  = __shfl_sync(0xffffffffu, cf, j*4 + 0);
            const float c1  = __shfl_sync(0xffffffffu, cf, j*4 + 1);
            const float c2  = __shfl_sync(0xffffffffu, cf, j*4 + 2);
            const float c3  = __shfl_sync(0xffffffffu, cf, j*4 + 3);
            const float ccj = __shfl_sync(0xffffffffu, cf, 16 + j);
            float4 o4;
            float* op = &o4.x;
            #pragma unroll
            for (int comp = 0; comp < 4; comp++) {
                float s = xc[j][comp];
                s = fmaf(c0, xc[0][comp], s);
                s = fmaf(c1, xc[1][comp], s);
                s = fmaf(c2, xc[2][comp], s);
                s = fmaf(c3, xc[3][comp], s);
                op[comp] = (s + innov[comp]*ccj) * sc[comp];
            }
            stcs4(out + ((size_t)j*NTOK + t)*HDIM + h4, o4);
        }
        // no trailing barrier: red ping-pongs by parity; same-parity reuse is
        // separated by the single barrier of the intervening iteration.
    }
}

extern "C" void kernel_launch(void* const* d_in, const int* in_sizes, int n_in,
                              void* d_out, int out_size)
{
    const float* hs     = (const float*)d_in[0];
    const float* act    = (const float*)d_in[1];
    const float* w      = (const float*)d_in[2];
    const float* rw     = (const float*)d_in[3];
    const float* pw     = (const float*)d_in[4];
    const float* cw     = (const float*)d_in[5];
    const float* oscale = (const float*)d_in[6];
    float* out = (float*)d_out;

    altup_v10_kernel<<<NCTAS, NTHREADS>>>(hs, act, w, rw, pw, cw, oscale, out);
}